// round 12
// baseline (speedup 1.0000x reference)
#include <cuda_runtime.h>
#include <cuda_bf16.h>
#include <math.h>
#include <stdint.h>

#define NUM_BINS 15
#define C 100
#define THREADS 256

// Global scratch. Zeroed at load; the finalizing block re-zeros for next replay.
__device__ float        g_conf[NUM_BINS];
__device__ float        g_acc[NUM_BINS];
__device__ unsigned int g_done;

struct Stage {
    float4 v0, v1, v2;
    float  vt;
    int    lbl;
    const float* rowp;
};

__global__ void __launch_bounds__(THREADS, 4) ece_kernel(
    const float* __restrict__ logits,
    const long long* __restrict__ labels,
    float* __restrict__ out,
    int n_rows, int n_groups, int total_blocks)
{
    __shared__ float s_conf[NUM_BINS];
    __shared__ float s_acc[NUM_BINS];

    const int tid = threadIdx.x;
    if (tid < NUM_BINS) { s_conf[tid] = 0.0f; s_acc[tid] = 0.0f; }
    __syncthreads();

    const int lane = tid & 31;
    const int a    = lane >> 3;          // row-in-group 0..3
    const int b    = lane & 7;           // lane-in-row  0..7
    const bool tail_lane = (b < 4);      // owns scalar element 96+b of its row
    const int warp_id   = (blockIdx.x * (THREADS / 32)) + (tid >> 5);
    const int num_warps = total_blocks * (THREADS / 32);

    auto load_stage = [&](int g) -> Stage {
        Stage r;
        int row = (g << 2) + a;
        r.rowp = logits + (size_t)row * C;
        const float4* rp = reinterpret_cast<const float4*>(r.rowp);
        r.v0 = __ldg(&rp[b]);
        r.v1 = __ldg(&rp[b + 8]);
        r.v2 = __ldg(&rp[b + 16]);
        r.vt = tail_lane ? __ldg(r.rowp + 96 + b) : -80.0f;
        r.lbl = (int)__ldg(&labels[row]);
        return r;
    };

    auto compute = [&](const Stage& q) {
        float e00 = __expf(q.v0.x), e01 = __expf(q.v0.y), e02 = __expf(q.v0.z), e03 = __expf(q.v0.w);
        float e10 = __expf(q.v1.x), e11 = __expf(q.v1.y), e12 = __expf(q.v1.z), e13 = __expf(q.v1.w);
        float e20 = __expf(q.v2.x), e21 = __expf(q.v2.y), e22 = __expf(q.v2.z), e23 = __expf(q.v2.w);
        float et  = __expf(q.vt);    // ~0 on non-tail lanes

        float em = fmaxf(fmaxf(fmaxf(e00, e01), fmaxf(e02, e03)),
                         fmaxf(fmaxf(e10, e11), fmaxf(e12, e13)));
        em = fmaxf(em, fmaxf(fmaxf(e20, e21), fmaxf(e22, e23)));
        em = fmaxf(em, et);

        float s = ((e00 + e01) + (e02 + e03))
                + ((e10 + e11) + (e12 + e13))
                + ((e20 + e21) + (e22 + e23))
                + et;

        #pragma unroll
        for (int o = 1; o <= 4; o <<= 1) {
            em = fmaxf(em, __shfl_xor_sync(0xffffffffu, em, o));
            s += __shfl_xor_sync(0xffffffffu, s, o);
        }

        if (b == 0) {
            int label = min(max(q.lbl, 0), C - 1);
            float lv = __ldg(q.rowp + label);     // L1/L2 hit: row streamed recently
            float inv    = __frcp_rn(s);
            float max_p  = em * inv;              // in (0, 1]
            float pred_p = __expf(lv) * inv;
            int bin = min((int)(max_p * (float)NUM_BINS), NUM_BINS - 1);
            atomicAdd(&s_conf[bin], max_p);
            atomicAdd(&s_acc[bin],  pred_p);
        }
    };

    // ---- depth-2 software pipeline over grid-strided 4-row groups ----
    int  g0 = warp_id;
    int  g1 = g0 + num_warps;
    bool h0 = g0 < n_groups;
    bool h1 = g1 < n_groups;

    Stage A, B;
    if (h0) A = load_stage(g0);
    if (h1) B = load_stage(g1);

    while (h0) {
        int  g2 = g1 + num_warps;
        bool h2 = g2 < n_groups;
        Stage Cs;
        if (h2) Cs = load_stage(g2);   // in flight for 2 full compute bodies

        compute(A);

        A = B; B = Cs;
        g0 = g1; g1 = g2;
        h0 = h1; h1 = h2;
    }

    // ---- remainder rows (n_rows % 4), block 0 only ----
    if (blockIdx.x == 0 && tid < 32) {
        int row = n_groups * 4 + lane;
        if (row < n_rows) {
            const float* rw = logits + (size_t)row * C;
            float em = 0.f, s = 0.f;
            for (int j = 0; j < C; j++) {
                float e = __expf(__ldg(rw + j));
                s += e; em = fmaxf(em, e);
            }
            int label = (int)__ldg(&labels[row]);
            label = min(max(label, 0), C - 1);
            float pe  = __expf(__ldg(rw + label));
            float inv = __frcp_rn(s);
            float max_p = em * inv, pred_p = pe * inv;
            int bin = min((int)(max_p * (float)NUM_BINS), NUM_BINS - 1);
            atomicAdd(&s_conf[bin], max_p);
            atomicAdd(&s_acc[bin],  pred_p);
        }
    }

    __syncthreads();
    if (tid < NUM_BINS) {
        float c  = s_conf[tid];
        float aa = s_acc[tid];
        if (c  != 0.0f) atomicAdd(&g_conf[tid], c);
        if (aa != 0.0f) atomicAdd(&g_acc[tid],  aa);
    }
    __syncthreads();
    __threadfence();

    if (tid == 0) {
        unsigned int ticket = atomicAdd(&g_done, 1u);
        if (ticket == (unsigned int)(total_blocks - 1)) {
            __threadfence();
            float e = 0.0f;
            #pragma unroll
            for (int bb = 0; bb < NUM_BINS; bb++) {
                e += fabsf(g_conf[bb] - g_acc[bb]);
                g_conf[bb] = 0.0f;      // self-clean for next graph replay
                g_acc[bb]  = 0.0f;
            }
            out[0] = e / (float)n_rows;
            g_done = 0u;
        }
    }
}

extern "C" void kernel_launch(void* const* d_in, const int* in_sizes, int n_in,
                              void* d_out, int out_size)
{
    const float*     logits = (const float*)d_in[0];
    const long long* labels = (const long long*)d_in[1];
    float* out = (float*)d_out;

    int n_rows   = in_sizes[1];          // labels element count = N
    int n_groups = n_rows >> 2;          // full 4-row groups

    int blocks = 148 * 4;                // one wave at 4 CTAs/SM (64-reg budget)
    int max_blocks = (n_groups + (THREADS / 32) - 1) / (THREADS / 32);
    if (blocks > max_blocks) blocks = max_blocks;
    if (blocks < 1) blocks = 1;

    ece_kernel<<<blocks, THREADS>>>(logits, labels, out, n_rows, n_groups, blocks);
}

// round 13
// speedup vs baseline: 1.0646x; 1.0646x over previous
#include <cuda_runtime.h>
#include <cuda_bf16.h>
#include <math.h>
#include <stdint.h>

#define NUM_BINS 15
#define C 100
#define THREADS 256

// Global scratch. Zeroed at load; the finalizing block re-zeros for next replay.
__device__ float        g_conf[NUM_BINS];
__device__ float        g_acc[NUM_BINS];
__device__ unsigned int g_done;

struct Stage {
    float4 v0, v1, v2;
    float  vt;
    int    lbl;
    const float* rowp;
};

__global__ void __launch_bounds__(THREADS, 5) ece_kernel(
    const float* __restrict__ logits,
    const long long* __restrict__ labels,
    float* __restrict__ out,
    int n_rows, int n_groups, int total_blocks)
{
    __shared__ float s_conf[NUM_BINS];
    __shared__ float s_acc[NUM_BINS];

    const int tid = threadIdx.x;
    if (tid < NUM_BINS) { s_conf[tid] = 0.0f; s_acc[tid] = 0.0f; }
    __syncthreads();

    const int lane = tid & 31;
    const int a    = lane >> 3;          // row-in-group 0..3
    const int b    = lane & 7;           // lane-in-row  0..7
    const bool tail_lane = (b < 4);      // owns scalar element 96+b of its row
    const int warp_id   = (blockIdx.x * (THREADS / 32)) + (tid >> 5);
    const int num_warps = total_blocks * (THREADS / 32);

    auto load_into = [&](Stage& r, int g) {
        int row = (g << 2) + a;
        r.rowp = logits + (size_t)row * C;
        const float4* rp = reinterpret_cast<const float4*>(r.rowp);
        r.v0 = __ldg(&rp[b]);
        r.v1 = __ldg(&rp[b + 8]);
        r.v2 = __ldg(&rp[b + 16]);
        r.vt = tail_lane ? __ldg(r.rowp + 96 + b) : -80.0f;
        r.lbl = (int)__ldg(&labels[row]);
    };

    auto compute = [&](const Stage& q) {
        float e00 = __expf(q.v0.x), e01 = __expf(q.v0.y), e02 = __expf(q.v0.z), e03 = __expf(q.v0.w);
        float e10 = __expf(q.v1.x), e11 = __expf(q.v1.y), e12 = __expf(q.v1.z), e13 = __expf(q.v1.w);
        float e20 = __expf(q.v2.x), e21 = __expf(q.v2.y), e22 = __expf(q.v2.z), e23 = __expf(q.v2.w);
        float et  = __expf(q.vt);    // ~0 on non-tail lanes

        float em = fmaxf(fmaxf(fmaxf(e00, e01), fmaxf(e02, e03)),
                         fmaxf(fmaxf(e10, e11), fmaxf(e12, e13)));
        em = fmaxf(em, fmaxf(fmaxf(e20, e21), fmaxf(e22, e23)));
        em = fmaxf(em, et);

        float s = ((e00 + e01) + (e02 + e03))
                + ((e10 + e11) + (e12 + e13))
                + ((e20 + e21) + (e22 + e23))
                + et;

        #pragma unroll
        for (int o = 1; o <= 4; o <<= 1) {
            em = fmaxf(em, __shfl_xor_sync(0xffffffffu, em, o));
            s += __shfl_xor_sync(0xffffffffu, s, o);
        }

        if (b == 0) {
            int label = min(max(q.lbl, 0), C - 1);
            float lv = __ldg(q.rowp + label);     // L1 hit: row streamed last iter
            float inv    = __frcp_rn(s);
            float max_p  = em * inv;              // in (0, 1]
            float pred_p = __expf(lv) * inv;
            int bin = min((int)(max_p * (float)NUM_BINS), NUM_BINS - 1);
            atomicAdd(&s_conf[bin], max_p);
            atomicAdd(&s_acc[bin],  pred_p);
        }
    };

    // ---- ping-pong depth-1 pipeline (no rotation MOVs: renaming via unroll-2) ----
    int  g    = warp_id;
    bool have = g < n_groups;
    Stage A, B;
    if (have) load_into(A, g);

    while (have) {
        int  gn = g + num_warps;
        bool hn = gn < n_groups;
        if (hn) load_into(B, gn);
        compute(A);
        g = gn; have = hn;
        if (!have) break;

        gn = g + num_warps;
        hn = gn < n_groups;
        if (hn) load_into(A, gn);
        compute(B);
        g = gn; have = hn;
    }

    // ---- remainder rows (n_rows % 4), block 0 only ----
    if (blockIdx.x == 0 && tid < 32) {
        int row = n_groups * 4 + lane;
        if (row < n_rows) {
            const float* rw = logits + (size_t)row * C;
            float em = 0.f, s = 0.f;
            for (int j = 0; j < C; j++) {
                float e = __expf(__ldg(rw + j));
                s += e; em = fmaxf(em, e);
            }
            int label = (int)__ldg(&labels[row]);
            label = min(max(label, 0), C - 1);
            float pe  = __expf(__ldg(rw + label));
            float inv = __frcp_rn(s);
            float max_p = em * inv, pred_p = pe * inv;
            int bin = min((int)(max_p * (float)NUM_BINS), NUM_BINS - 1);
            atomicAdd(&s_conf[bin], max_p);
            atomicAdd(&s_acc[bin],  pred_p);
        }
    }

    __syncthreads();
    if (tid < NUM_BINS) {
        float c  = s_conf[tid];
        float aa = s_acc[tid];
        if (c  != 0.0f) atomicAdd(&g_conf[tid], c);
        if (aa != 0.0f) atomicAdd(&g_acc[tid],  aa);
    }
    __syncthreads();
    __threadfence();

    if (tid == 0) {
        unsigned int ticket = atomicAdd(&g_done, 1u);
        if (ticket == (unsigned int)(total_blocks - 1)) {
            __threadfence();
            float e = 0.0f;
            #pragma unroll
            for (int bb = 0; bb < NUM_BINS; bb++) {
                e += fabsf(g_conf[bb] - g_acc[bb]);
                g_conf[bb] = 0.0f;      // self-clean for next graph replay
                g_acc[bb]  = 0.0f;
            }
            out[0] = e / (float)n_rows;
            g_done = 0u;
        }
    }
}

extern "C" void kernel_launch(void* const* d_in, const int* in_sizes, int n_in,
                              void* d_out, int out_size)
{
    const float*     logits = (const float*)d_in[0];
    const long long* labels = (const long long*)d_in[1];
    float* out = (float*)d_out;

    int n_rows   = in_sizes[1];          // labels element count = N
    int n_groups = n_rows >> 2;          // full 4-row groups

    int blocks = 148 * 5;                // one wave at 5 CTAs/SM
    int max_blocks = (n_groups + (THREADS / 32) - 1) / (THREADS / 32);
    if (blocks > max_blocks) blocks = max_blocks;
    if (blocks < 1) blocks = 1;

    ece_kernel<<<blocks, THREADS>>>(logits, labels, out, n_rows, n_groups, blocks);
}

// round 14
// speedup vs baseline: 1.1390x; 1.0698x over previous
#include <cuda_runtime.h>
#include <cuda_bf16.h>
#include <math.h>
#include <stdint.h>

#define NUM_BINS 15
#define C 100
#define THREADS 256
#define WARPS_PER_BLOCK 8

// Global scratch. Zeroed at load; the finalizing block re-zeros for next replay.
__device__ float        g_conf[NUM_BINS];
__device__ float        g_acc[NUM_BINS];
__device__ unsigned int g_done;

__device__ __forceinline__ void cp_async16(uint32_t smem_dst, const void* gmem_src) {
    asm volatile("cp.async.cg.shared.global [%0], [%1], 16;\n"
                 :: "r"(smem_dst), "l"(gmem_src));
}
__device__ __forceinline__ void cp_commit() {
    asm volatile("cp.async.commit_group;\n" ::: "memory");
}
__device__ __forceinline__ void cp_wait1() {
    asm volatile("cp.async.wait_group 1;\n" ::: "memory");
}
__device__ __forceinline__ void cp_wait0() {
    asm volatile("cp.async.wait_group 0;\n" ::: "memory");
}

__global__ void __launch_bounds__(THREADS, 6) ece_kernel(
    const float* __restrict__ logits,
    const long long* __restrict__ labels,
    float* __restrict__ out,
    int n_rows, int n_groups, int total_blocks)
{
    // Per-warp private double buffers: 8 warps x 2 x (4 rows x 100 floats)
    __shared__ alignas(16) float     tile[WARPS_PER_BLOCK][2][4 * C]; // 25,600 B
    __shared__ alignas(16) long long labs[WARPS_PER_BLOCK][2][4];     //    512 B
    __shared__ float s_conf[NUM_BINS];
    __shared__ float s_acc[NUM_BINS];

    const int tid  = threadIdx.x;
    if (tid < NUM_BINS) { s_conf[tid] = 0.0f; s_acc[tid] = 0.0f; }
    __syncthreads();

    const int w    = tid >> 5;
    const int lane = tid & 31;
    const int a    = lane >> 3;          // row-in-group 0..3
    const int b    = lane & 7;           // lane-in-row  0..7
    const int warp_id   = blockIdx.x * WARPS_PER_BLOCK + w;
    const int num_warps = total_blocks * WARPS_PER_BLOCK;

    // ---- stage group g into buffer k: 100 x 16B + labels, coalesced ----
    auto stage = [&](int k, int g) {
        const float* src = logits + (size_t)g * (4 * C);
        uint32_t d = (uint32_t)__cvta_generic_to_shared(&tile[w][k][0]);
        cp_async16(d + (lane      ) * 16, src + (lane      ) * 4);
        cp_async16(d + (lane + 32 ) * 16, src + (lane + 32 ) * 4);
        cp_async16(d + (lane + 64 ) * 16, src + (lane + 64 ) * 4);
        if (lane < 4)
            cp_async16(d + (lane + 96) * 16, src + (lane + 96) * 4);
        if (lane < 2) {
            uint32_t ld = (uint32_t)__cvta_generic_to_shared(&labs[w][k][0]);
            cp_async16(ld + lane * 16, labels + (size_t)g * 4 + lane * 2);
        }
    };

    // ---- compute group from buffer k (R11-verified body, smem source) ----
    auto compute = [&](int k) {
        const float* base = &tile[w][k][a * C];       // 400B-aligned
        float4 v0 = *reinterpret_cast<const float4*>(base + 4 * b);
        float4 v1 = *reinterpret_cast<const float4*>(base + 4 * (b + 8));
        float4 v2 = *reinterpret_cast<const float4*>(base + 4 * (b + 16));
        float  vt = (b < 4) ? base[96 + b] : -80.0f;

        float e00 = __expf(v0.x), e01 = __expf(v0.y), e02 = __expf(v0.z), e03 = __expf(v0.w);
        float e10 = __expf(v1.x), e11 = __expf(v1.y), e12 = __expf(v1.z), e13 = __expf(v1.w);
        float e20 = __expf(v2.x), e21 = __expf(v2.y), e22 = __expf(v2.z), e23 = __expf(v2.w);
        float et  = __expf(vt);   // ~0 on non-tail lanes

        float em = fmaxf(fmaxf(fmaxf(e00, e01), fmaxf(e02, e03)),
                         fmaxf(fmaxf(e10, e11), fmaxf(e12, e13)));
        em = fmaxf(em, fmaxf(fmaxf(e20, e21), fmaxf(e22, e23)));
        em = fmaxf(em, et);

        float s = ((e00 + e01) + (e02 + e03))
                + ((e10 + e11) + (e12 + e13))
                + ((e20 + e21) + (e22 + e23))
                + et;

        #pragma unroll
        for (int o = 1; o <= 4; o <<= 1) {
            em = fmaxf(em, __shfl_xor_sync(0xffffffffu, em, o));
            s += __shfl_xor_sync(0xffffffffu, s, o);
        }

        if (b == 0) {
            int label = min(max((int)labs[w][k][a], 0), C - 1);
            float lv = base[label];                    // smem read, no L2 trip
            float inv    = __frcp_rn(s);
            float max_p  = em * inv;                   // in (0, 1]
            float pred_p = __expf(lv) * inv;
            int bin = min((int)(max_p * (float)NUM_BINS), NUM_BINS - 1);
            atomicAdd(&s_conf[bin], max_p);
            atomicAdd(&s_acc[bin],  pred_p);
        }
    };

    // ---- per-warp depth-2 cp.async pipeline over grid-strided groups ----
    int g = warp_id;
    bool have = g < n_groups;
    if (have) stage(0, g);
    cp_commit();
    if (g + num_warps < n_groups) stage(1, g + num_warps);
    cp_commit();

    int cur = 0;
    while (have) {
        cp_wait1();              // oldest group (buffer cur) landed
        __syncwarp();
        compute(cur);
        __syncwarp();            // all lanes done reading before overwrite
        int g2 = g + 2 * num_warps;
        if (g2 < n_groups) stage(cur, g2);
        cp_commit();             // empty commits keep FIFO accounting uniform
        cur ^= 1;
        g += num_warps;
        have = g < n_groups;
    }
    cp_wait0();
    __syncwarp();

    // ---- remainder rows (n_rows % 4), block 0 only ----
    if (blockIdx.x == 0 && tid < 32) {
        int row = n_groups * 4 + lane;
        if (row < n_rows) {
            const float* rw = logits + (size_t)row * C;
            float em = 0.f, s = 0.f;
            for (int j = 0; j < C; j++) {
                float e = __expf(__ldg(rw + j));
                s += e; em = fmaxf(em, e);
            }
            int label = (int)__ldg(&labels[row]);
            label = min(max(label, 0), C - 1);
            float pe  = __expf(__ldg(rw + label));
            float inv = __frcp_rn(s);
            float max_p = em * inv, pred_p = pe * inv;
            int bin = min((int)(max_p * (float)NUM_BINS), NUM_BINS - 1);
            atomicAdd(&s_conf[bin], max_p);
            atomicAdd(&s_acc[bin],  pred_p);
        }
    }

    __syncthreads();
    if (tid < NUM_BINS) {
        float c  = s_conf[tid];
        float aa = s_acc[tid];
        if (c  != 0.0f) atomicAdd(&g_conf[tid], c);
        if (aa != 0.0f) atomicAdd(&g_acc[tid],  aa);
    }
    __syncthreads();
    __threadfence();

    if (tid == 0) {
        unsigned int ticket = atomicAdd(&g_done, 1u);
        if (ticket == (unsigned int)(total_blocks - 1)) {
            __threadfence();
            float e = 0.0f;
            #pragma unroll
            for (int bb = 0; bb < NUM_BINS; bb++) {
                e += fabsf(g_conf[bb] - g_acc[bb]);
                g_conf[bb] = 0.0f;      // self-clean for next graph replay
                g_acc[bb]  = 0.0f;
            }
            out[0] = e / (float)n_rows;
            g_done = 0u;
        }
    }
}

extern "C" void kernel_launch(void* const* d_in, const int* in_sizes, int n_in,
                              void* d_out, int out_size)
{
    const float*     logits = (const float*)d_in[0];
    const long long* labels = (const long long*)d_in[1];
    float* out = (float*)d_out;

    int n_rows   = in_sizes[1];          // labels element count = N
    int n_groups = n_rows >> 2;          // full 4-row groups

    int blocks = 148 * 6;                // one wave at 6 CTAs/SM
    int max_blocks = (n_groups + WARPS_PER_BLOCK - 1) / WARPS_PER_BLOCK;
    if (blocks > max_blocks) blocks = max_blocks;
    if (blocks < 1) blocks = 1;

    ece_kernel<<<blocks, THREADS>>>(logits, labels, out, n_rows, n_groups, blocks);
}